// round 3
// baseline (speedup 1.0000x reference)
#include <cuda_runtime.h>
#include <cuda_bf16.h>
#include <cstdint>
#include <cstddef>

#define B_  8
#define C_  512
#define NPIX_ 4096
#define IN_ 32

// ---------------- scratch ----------------
__device__ float g_S[B_ * C_ * 9];
__device__ __nv_bfloat16 g_fbf1[B_ * 9216];            // dyn filter 1, mma layout
__device__ __nv_bfloat16 g_fbf2[B_ * 9216];            // dyn filter 2, mma layout
__device__ __nv_bfloat16 g_c0[B_ * IN_ * NPIX_];
__device__ __nv_bfloat16 g_c1[B_ * IN_ * NPIX_];
__device__ __nv_bfloat16 g_c2[B_ * IN_ * NPIX_];
__device__ float g_part[3 * B_ * IN_ * NPIX_];         // ds split-K partials (fp32)
__device__ __nv_bfloat16 g_wt_ds[9 * 32 * C_];         // [9][32 chunks][32 oc][16]
__device__ __nv_bfloat16 g_wt_up[9 * 2 * C_ * 16];     // [9][2 chunks][512 oc][16]

static __device__ __forceinline__ __nv_bfloat16 to_bf(float v)         { return __float2bfloat16_rn(v); }
static __device__ __forceinline__ __nv_bfloat16 to_bf(__nv_bfloat16 v) { return v; }

// ============================================================================
// Style reduction (border-aware channel sums)
// ============================================================================
__global__ void style_reduce_kernel(const float* __restrict__ style,
                                    float* __restrict__ S)
{
    const int i = blockIdx.x, b = blockIdx.y, t = threadIdx.x;
    const float* p = style + ((size_t)(b * C_ + i)) * NPIX_;

    float T = 0.f, R0 = 0.f, R63 = 0.f, Ca = 0.f, Cb = 0.f;
    #pragma unroll
    for (int k = 0; k < 4; k++) {
        int idx4 = t + k * 256;
        float4 v = reinterpret_cast<const float4*>(p)[idx4];
        int y = idx4 >> 4, xq = idx4 & 15;
        float s = v.x + v.y + v.z + v.w;
        T += s;
        if (y == 0)   R0  += s;
        if (y == 63)  R63 += s;
        if (xq == 0)  Ca  += v.x;
        if (xq == 15) Cb  += v.w;
    }
    __shared__ float red[5][8];
    float vals[5] = {T, R0, R63, Ca, Cb};
    const int lane = t & 31, wid = t >> 5;
    #pragma unroll
    for (int j = 0; j < 5; j++) {
        float v = vals[j];
        #pragma unroll
        for (int off = 16; off; off >>= 1) v += __shfl_xor_sync(0xffffffffu, v, off);
        if (lane == 0) red[j][wid] = v;
    }
    __syncthreads();
    if (t == 0) {
        float tv[5];
        #pragma unroll
        for (int j = 0; j < 5; j++) {
            float s = 0.f;
            #pragma unroll
            for (int wq = 0; wq < 8; wq++) s += red[j][wq];
            tv[j] = s;
        }
        const float c00 = p[0], c0e = p[63], ce0 = p[63 * 64], cee = p[63 * 64 + 63];
        float* out = S + (size_t)(b * C_ + i) * 9;
        #pragma unroll
        for (int ky = 0; ky < 3; ky++)
            #pragma unroll
            for (int kx = 0; kx < 3; kx++) {
                float s = tv[0];
                if (ky == 0) s -= tv[2];
                if (ky == 2) s -= tv[1];
                if (kx == 0) s -= tv[4];
                if (kx == 2) s -= tv[3];
                if (ky == 0 && kx == 0) s += cee;
                if (ky == 0 && kx == 2) s += ce0;
                if (ky == 2 && kx == 0) s += c0e;
                if (ky == 2 && kx == 2) s += c00;
                out[ky * 3 + kx] = s;
            }
    }
}

// ============================================================================
// Filter prediction -> writes dyn filters DIRECTLY in bf16 mma layout
// out[((tap*2 + ic/16)*32 + oc)*16 + ic%16]
// ============================================================================
__global__ void predict_kernel(const float* __restrict__ S,
                               const float* __restrict__ cw1, const float* __restrict__ cb1,
                               const float* __restrict__ fw1, const float* __restrict__ fb1,
                               const float* __restrict__ cw2, const float* __restrict__ cb2,
                               const float* __restrict__ fw2, const float* __restrict__ fb2,
                               __nv_bfloat16* __restrict__ fo1, __nv_bfloat16* __restrict__ fo2)
{
    const int b = blockIdx.x, t = threadIdx.x;
    __shared__ float red[256];
    __shared__ float pooled[64];
    const float* Sb = S + (size_t)b * C_ * 9;
    {
        const int o = t & 63, part = t >> 6, oo = o & 31;
        const float* cw = (o < 32) ? cw1 : cw2;
        const float* cwp = cw + (size_t)oo * (C_ * 9) + part * 128 * 9;
        const float* Sp  = Sb + part * 128 * 9;
        float s0 = 0.f, s1 = 0.f;
        #pragma unroll 4
        for (int k = 0; k < 1152; k += 2) {
            s0 = fmaf(cwp[k], Sp[k], s0);
            s1 = fmaf(cwp[k + 1], Sp[k + 1], s1);
        }
        red[t] = s0 + s1;
    }
    __syncthreads();
    if (t < 64) {
        float tot = red[t] + red[t + 64] + red[t + 128] + red[t + 192];
        float cb = (t < 32) ? cb1[t] : cb2[t - 32];
        pooled[t] = tot * (1.f / 4096.f) + cb;
    }
    __syncthreads();
    for (int j = t; j < 2 * 9216; j += 256) {
        const bool first = (j < 9216);
        const int jj = first ? j : j - 9216;
        const float* fw = first ? fw1 : fw2;
        const float* fb = first ? fb1 : fb2;
        const float* pp = pooled + (first ? 0 : 32);
        float v = fb[jj];
        const float4* fw4 = reinterpret_cast<const float4*>(fw + (size_t)jj * 32);
        #pragma unroll
        for (int q = 0; q < 8; q++) {
            float4 wv = fw4[q];
            v = fmaf(wv.x, pp[q * 4 + 0], v);
            v = fmaf(wv.y, pp[q * 4 + 1], v);
            v = fmaf(wv.z, pp[q * 4 + 2], v);
            v = fmaf(wv.w, pp[q * 4 + 3], v);
        }
        // jj = oc*288 + ic*9 + tap  ->  mma layout
        int oc = jj / 288;
        int r2 = jj - oc * 288;
        int ic = r2 / 9;
        int tap = r2 - ic * 9;
        int oidx = ((tap * 2 + (ic >> 4)) * 32 + oc) * 16 + (ic & 15);
        (first ? fo1 : fo2)[(size_t)b * 9216 + oidx] = __float2bfloat16_rn(v);
    }
}

// ============================================================================
// Static weight transpose: W[oc][ic][tap] fp32 -> [tap][ic/16][oc][16] bf16
// ============================================================================
__global__ void wtrans_kernel(const float* __restrict__ w, __nv_bfloat16* __restrict__ wt,
                              int cin, int cout)
{
    int idx = blockIdx.x * 256 + threadIdx.x;
    int total = cout * cin * 9;
    if (idx >= total) return;
    int i16 = idx & 15;
    int oc  = (idx >> 4) % cout;
    int rest = idx / (16 * cout);
    int nch = cin >> 4;
    int chunk = rest % nch;
    int tap = rest / nch;
    int ic = chunk * 16 + i16;
    wt[idx] = __float2bfloat16_rn(w[((size_t)oc * cin + ic) * 9 + tap]);
}

// ============================================================================
// Tensor-core 3x3 conv, tap-decomposed implicit GEMM.
// EPI: 0 = fp32 partial, 1 = bf16, 2 = bf16+lrelu, 3 = fp32+bias+resid
// PREF: register double-buffer of next ic-chunk (tile + weights)
// ============================================================================
__device__ __forceinline__ void mma16816(float* c, const uint32_t* a, const uint32_t* b)
{
    asm volatile(
        "mma.sync.aligned.m16n8k16.row.col.f32.bf16.bf16.f32 "
        "{%0,%1,%2,%3}, {%4,%5,%6,%7}, {%8,%9}, {%0,%1,%2,%3};\n"
        : "+f"(c[0]), "+f"(c[1]), "+f"(c[2]), "+f"(c[3])
        : "r"(a[0]), "r"(a[1]), "r"(a[2]), "r"(a[3]), "r"(b[0]), "r"(b[1]));
}

template <int MT, int NFRAG, bool SPLIT, int EPI, typename TI, bool PREF>
__global__ void __launch_bounds__(256)
conv_mma_kernel(const TI* __restrict__ x, const __nv_bfloat16* __restrict__ wt,
                const float* __restrict__ bias, const float* __restrict__ resid,
                void* __restrict__ y, int cin, int cout, int wstride)
{
    __shared__ __align__(16) __nv_bfloat16 s_x[6 * 66 * 18];
    __shared__ __align__(16) __nv_bfloat16 s_a[9 * MT * 16];

    const int b  = blockIdx.z;
    const int ty = blockIdx.x * 4;
    const int t  = threadIdx.x;
    const int wid = t >> 5, lane = t & 31;
    const int g = lane >> 2, t4 = lane & 3;

    int chunk0, nch, ocb;
    if (SPLIT) {
        int s = blockIdx.y;
        chunk0 = s * 11; nch = (s == 2) ? 10 : 11; ocb = 0;
    } else {
        ocb = blockIdx.y * MT; chunk0 = 0; nch = cin >> 4;
    }

    const int wm = (MT == 32) ? 0 : (wid >> 2) * 32;
    const int nb = (MT == 32) ? wid * 32 : (wid & 3) * 64;

    int bBase[NFRAG];
    #pragma unroll
    for (int f = 0; f < NFRAG; f++) {
        int n = nb + f * 8 + g;
        int r = n >> 6, cc = n & 63;
        bBase[f] = (r * 66 + cc) * 9 + t4;
    }

    float acc[2][NFRAG][4];
    #pragma unroll
    for (int mf = 0; mf < 2; mf++)
        #pragma unroll
        for (int f = 0; f < NFRAG; f++)
            #pragma unroll
            for (int q = 0; q < 4; q++) acc[mf][f][q] = 0.f;

    const TI* xb = x + (size_t)b * cin * NPIX_;
    const __nv_bfloat16* wb = wt + (size_t)b * wstride;
    const uint32_t* s_xu = reinterpret_cast<const uint32_t*>(s_x);
    const uint32_t* s_au = reinterpret_cast<const uint32_t*>(s_a);
    uint32_t* s_au_w = reinterpret_cast<uint32_t*>(s_a);
    const int nch16 = cin >> 4;
    const int WPER = MT * 8;           // u32 per tap slice
    const int NLD  = 25;               // ceil(6336/256)
    const int WLD  = (9 * WPER) / 256; // 9 for MT=32, 18 for MT=64

    // ---- direct staging of chunk `c` ----
    auto stage_direct = [&](int c) {
        for (int k = 0; k < NLD; k++) {
            int idx = t + k * 256;
            if (idx < 6336) {
                int rowid = idx / 66;
                int x_ = idx - rowid * 66;
                int ic = rowid / 6;
                int y_ = rowid - ic * 6;
                int gy = ty + y_ - 1, gx = x_ - 1;
                float v = 0.f;
                __nv_bfloat16 hv = __float2bfloat16_rn(0.f);
                if ((unsigned)gy < 64u && (unsigned)gx < 64u)
                    hv = to_bf(xb[(size_t)(c * 16 + ic) * NPIX_ + gy * 64 + gx]);
                s_x[(y_ * 66 + x_) * 18 + ic] = hv;
            }
        }
        for (int k = 0; k < WLD; k++) {
            int idx = t + k * 256;
            int tap = idx / WPER;
            int j = idx - tap * WPER;
            const uint32_t* src = reinterpret_cast<const uint32_t*>(
                wb + ((size_t)(tap * nch16 + c) * cout + ocb) * 16);
            s_au_w[tap * WPER + j] = src[j];
        }
    };

    // ---- compute on currently staged chunk ----
    auto compute = [&]() {
        #pragma unroll
        for (int tap = 0; tap < 9; tap++) {
            const int dy = tap / 3, dx = tap - dy * 3;
            uint32_t a[2][4];
            #pragma unroll
            for (int mf = 0; mf < 2; mf++) {
                int oc0 = wm + mf * 16 + g;
                int base = (tap * MT + oc0) * 8 + t4;
                a[mf][0] = s_au[base];
                a[mf][1] = s_au[base + 8 * 8];
                a[mf][2] = s_au[base + 4];
                a[mf][3] = s_au[base + 8 * 8 + 4];
            }
            const int shift = (dy * 66 + dx) * 9;
            uint32_t bf[NFRAG][2];
            #pragma unroll
            for (int f = 0; f < NFRAG; f++) {
                int u = bBase[f] + shift;
                bf[f][0] = s_xu[u];
                bf[f][1] = s_xu[u + 4];
            }
            #pragma unroll
            for (int mf = 0; mf < 2; mf++)
                #pragma unroll
                for (int f = 0; f < NFRAG; f++)
                    mma16816(acc[mf][f], a[mf], bf[f]);
        }
    };

    stage_direct(chunk0);
    __syncthreads();

    if (PREF) {
        TI xv[NLD];
        uint32_t wv[WLD];
        for (int c = chunk0; c < chunk0 + nch; c++) {
            const bool more = (c + 1 < chunk0 + nch);
            if (more) {
                int cn = c + 1;
                #pragma unroll
                for (int k = 0; k < NLD; k++) {
                    int idx = t + k * 256;
                    xv[k] = TI(0.f);
                    if (idx < 6336) {
                        int rowid = idx / 66;
                        int x_ = idx - rowid * 66;
                        int ic = rowid / 6;
                        int y_ = rowid - ic * 6;
                        int gy = ty + y_ - 1, gx = x_ - 1;
                        if ((unsigned)gy < 64u && (unsigned)gx < 64u)
                            xv[k] = xb[(size_t)(cn * 16 + ic) * NPIX_ + gy * 64 + gx];
                    }
                }
                #pragma unroll
                for (int k = 0; k < WLD; k++) {
                    int idx = t + k * 256;
                    int tap = idx / WPER;
                    int j = idx - tap * WPER;
                    const uint32_t* src = reinterpret_cast<const uint32_t*>(
                        wb + ((size_t)(tap * nch16 + cn) * cout + ocb) * 16);
                    wv[k] = src[j];
                }
            }
            compute();
            if (more) {
                __syncthreads();
                #pragma unroll
                for (int k = 0; k < NLD; k++) {
                    int idx = t + k * 256;
                    if (idx < 6336) {
                        int rowid = idx / 66;
                        int x_ = idx - rowid * 66;
                        int ic = rowid / 6;
                        int y_ = rowid - ic * 6;
                        s_x[(y_ * 66 + x_) * 18 + ic] = to_bf(xv[k]);
                    }
                }
                #pragma unroll
                for (int k = 0; k < WLD; k++) {
                    int idx = t + k * 256;
                    int tap = idx / WPER;
                    int j = idx - tap * WPER;
                    s_au_w[tap * WPER + j] = wv[k];
                }
                __syncthreads();
            }
        }
    } else {
        for (int c = chunk0; c < chunk0 + nch; c++) {
            compute();
            if (c + 1 < chunk0 + nch) {
                __syncthreads();
                stage_direct(c + 1);
                __syncthreads();
            }
        }
    }

    // ---- epilogue ----
    #pragma unroll
    for (int mf = 0; mf < 2; mf++) {
        int oc0 = ocb + wm + mf * 16 + g;
        #pragma unroll
        for (int rr = 0; rr < 2; rr++) {
            int oc = oc0 + rr * 8;
            float bv = (EPI == 3 && bias) ? bias[oc] : 0.f;
            #pragma unroll
            for (int f = 0; f < NFRAG; f++) {
                int n = nb + f * 8 + t4 * 2;
                size_t off = (size_t)oc * NPIX_ + (size_t)(ty * 64) + n;
                float u0 = acc[mf][f][rr * 2 + 0];
                float u1 = acc[mf][f][rr * 2 + 1];
                if (EPI == 2) {
                    u0 = (u0 >= 0.f) ? u0 : 0.2f * u0;
                    u1 = (u1 >= 0.f) ? u1 : 0.2f * u1;
                }
                if (EPI == 0) {
                    float* yb = (float*)y + ((size_t)(blockIdx.y * B_ + b)) * (IN_ * NPIX_);
                    *reinterpret_cast<float2*>(yb + off) = make_float2(u0, u1);
                } else if (EPI == 3) {
                    float* yb = (float*)y + (size_t)b * cout * NPIX_;
                    float2 rv = *reinterpret_cast<const float2*>(
                        resid + (size_t)b * cout * NPIX_ + off);
                    *reinterpret_cast<float2*>(yb + off) =
                        make_float2(u0 + bv + rv.x, u1 + bv + rv.y);
                } else {
                    __nv_bfloat16* yb = (__nv_bfloat16*)y + (size_t)b * cout * NPIX_;
                    __nv_bfloat162 h;
                    h.x = __float2bfloat16_rn(u0);
                    h.y = __float2bfloat16_rn(u1);
                    *reinterpret_cast<__nv_bfloat162*>(yb + off) = h;
                }
            }
        }
    }
}

// ============================================================================
// Combine ds split-K partials + bias -> bf16 c0
// ============================================================================
__global__ void combine_kernel(const float* __restrict__ part,
                               const float* __restrict__ bias,
                               __nv_bfloat16* __restrict__ out)
{
    int i = blockIdx.x * 256 + threadIdx.x;   // float4 group index (262144 total)
    const float4* p0 = reinterpret_cast<const float4*>(part);
    const float4* p1 = p0 + 262144;
    const float4* p2 = p1 + 262144;
    float4 a = p0[i], bq = p1[i], cq = p2[i];
    float bv = bias[(i >> 10) & 31];
    __nv_bfloat162 h0, h1;
    h0.x = __float2bfloat16_rn(a.x + bq.x + cq.x + bv);
    h0.y = __float2bfloat16_rn(a.y + bq.y + cq.y + bv);
    h1.x = __float2bfloat16_rn(a.z + bq.z + cq.z + bv);
    h1.y = __float2bfloat16_rn(a.w + bq.w + cq.w + bv);
    reinterpret_cast<__nv_bfloat162*>(out)[2 * i]     = h0;
    reinterpret_cast<__nv_bfloat162*>(out)[2 * i + 1] = h1;
}

// ============================================================================
extern "C" void kernel_launch(void* const* d_in, const int* in_sizes, int n_in,
                              void* d_out, int out_size)
{
    const float* content = (const float*)d_in[0];
    const float* style   = (const float*)d_in[1];
    const float* ds_w    = (const float*)d_in[2];
    const float* ds_b    = (const float*)d_in[3];
    const float* up_w    = (const float*)d_in[4];
    const float* up_b    = (const float*)d_in[5];
    const float* f1_cw   = (const float*)d_in[6];
    const float* f1_cb   = (const float*)d_in[7];
    const float* f1_fw   = (const float*)d_in[8];
    const float* f1_fb   = (const float*)d_in[9];
    const float* f2_cw   = (const float*)d_in[10];
    const float* f2_cb   = (const float*)d_in[11];
    const float* f2_fw   = (const float*)d_in[12];
    const float* f2_fb   = (const float*)d_in[13];
    float* out = (float*)d_out;

    float *pS, *pPart;
    __nv_bfloat16 *pF1, *pF2, *pC0, *pC1, *pC2, *pWds, *pWup;
    cudaGetSymbolAddress((void**)&pS,  g_S);
    cudaGetSymbolAddress((void**)&pF1, g_fbf1);
    cudaGetSymbolAddress((void**)&pF2, g_fbf2);
    cudaGetSymbolAddress((void**)&pC0, g_c0);
    cudaGetSymbolAddress((void**)&pC1, g_c1);
    cudaGetSymbolAddress((void**)&pC2, g_c2);
    cudaGetSymbolAddress((void**)&pPart, g_part);
    cudaGetSymbolAddress((void**)&pWds, g_wt_ds);
    cudaGetSymbolAddress((void**)&pWup, g_wt_up);

    // style path
    style_reduce_kernel<<<dim3(C_, B_), 256>>>(style, pS);
    predict_kernel<<<B_, 256>>>(pS, f1_cw, f1_cb, f1_fw, f1_fb,
                                    f2_cw, f2_cb, f2_fw, f2_fb, pF1, pF2);

    // static weight transposes
    wtrans_kernel<<<576, 256>>>(ds_w, pWds, C_, IN_);
    wtrans_kernel<<<576, 256>>>(up_w, pWup, IN_, C_);

    // ds conv (split-K=3, fp32 input, register double-buffered) -> partials
    conv_mma_kernel<32, 4, true, 0, float, true><<<dim3(16, 3, B_), 256>>>(
        content, pWds, nullptr, nullptr, pPart, C_, IN_, 0);

    // combine + bias -> bf16 c0
    combine_kernel<<<1024, 256>>>(pPart, ds_b, pC0);

    // dyn conv 1 (+lrelu) and 2, tensor core, bf16 in/out
    conv_mma_kernel<32, 4, false, 2, __nv_bfloat16, false><<<dim3(16, 1, B_), 256>>>(
        pC0, pF1, nullptr, nullptr, pC1, IN_, IN_, 9216);
    conv_mma_kernel<32, 4, false, 1, __nv_bfloat16, false><<<dim3(16, 1, B_), 256>>>(
        pC1, pF2, nullptr, nullptr, pC2, IN_, IN_, 9216);

    // up conv + bias + residual (fp32 out)
    conv_mma_kernel<64, 8, false, 3, __nv_bfloat16, false><<<dim3(16, 8, B_), 256>>>(
        pC2, pWup, up_b, content, out, IN_, C_, 0);
}

// round 4
// speedup vs baseline: 1.2604x; 1.2604x over previous
#include <cuda_runtime.h>
#include <cuda_bf16.h>
#include <cstdint>
#include <cstddef>

#define B_  8
#define C_  512
#define NPIX_ 4096
#define IN_ 32

// ---------------- scratch ----------------
__device__ float g_S[B_ * C_ * 9];
__device__ __nv_bfloat16 g_fbf1[B_ * 9216];
__device__ __nv_bfloat16 g_fbf2[B_ * 9216];
__device__ __nv_bfloat16 g_c0[B_ * IN_ * NPIX_];
__device__ __nv_bfloat16 g_c1[B_ * IN_ * NPIX_];
__device__ __nv_bfloat16 g_c2[B_ * IN_ * NPIX_];
__device__ float g_part[3 * B_ * IN_ * NPIX_];
__device__ __nv_bfloat16 g_wt_ds[147456];   // [9][32][32][16]
__device__ __nv_bfloat16 g_wt_up[147456];   // [9][2][512][16]

// ============================================================================
// Style reduction
// ============================================================================
__global__ void style_reduce_kernel(const float* __restrict__ style,
                                    float* __restrict__ S)
{
    const int i = blockIdx.x, b = blockIdx.y, t = threadIdx.x;
    const float* p = style + ((size_t)(b * C_ + i)) * NPIX_;

    float T = 0.f, R0 = 0.f, R63 = 0.f, Ca = 0.f, Cb = 0.f;
    #pragma unroll
    for (int k = 0; k < 4; k++) {
        int idx4 = t + k * 256;
        float4 v = reinterpret_cast<const float4*>(p)[idx4];
        int y = idx4 >> 4, xq = idx4 & 15;
        float s = v.x + v.y + v.z + v.w;
        T += s;
        if (y == 0)   R0  += s;
        if (y == 63)  R63 += s;
        if (xq == 0)  Ca  += v.x;
        if (xq == 15) Cb  += v.w;
    }
    __shared__ float red[5][8];
    float vals[5] = {T, R0, R63, Ca, Cb};
    const int lane = t & 31, wid = t >> 5;
    #pragma unroll
    for (int j = 0; j < 5; j++) {
        float v = vals[j];
        #pragma unroll
        for (int off = 16; off; off >>= 1) v += __shfl_xor_sync(0xffffffffu, v, off);
        if (lane == 0) red[j][wid] = v;
    }
    __syncthreads();
    if (t == 0) {
        float tv[5];
        #pragma unroll
        for (int j = 0; j < 5; j++) {
            float s = 0.f;
            #pragma unroll
            for (int wq = 0; wq < 8; wq++) s += red[j][wq];
            tv[j] = s;
        }
        const float c00 = p[0], c0e = p[63], ce0 = p[63 * 64], cee = p[63 * 64 + 63];
        float* out = S + (size_t)(b * C_ + i) * 9;
        #pragma unroll
        for (int ky = 0; ky < 3; ky++)
            #pragma unroll
            for (int kx = 0; kx < 3; kx++) {
                float s = tv[0];
                if (ky == 0) s -= tv[2];
                if (ky == 2) s -= tv[1];
                if (kx == 0) s -= tv[4];
                if (kx == 2) s -= tv[3];
                if (ky == 0 && kx == 0) s += cee;
                if (ky == 0 && kx == 2) s += ce0;
                if (ky == 2 && kx == 0) s += c0e;
                if (ky == 2 && kx == 2) s += c00;
                out[ky * 3 + kx] = s;
            }
    }
}

// ============================================================================
// Filter prediction -> bf16 filters in mma layout [tap][chunk][oc][16]
// ============================================================================
__global__ void predict_kernel(const float* __restrict__ S,
                               const float* __restrict__ cw1, const float* __restrict__ cb1,
                               const float* __restrict__ fw1, const float* __restrict__ fb1,
                               const float* __restrict__ cw2, const float* __restrict__ cb2,
                               const float* __restrict__ fw2, const float* __restrict__ fb2,
                               __nv_bfloat16* __restrict__ fo1, __nv_bfloat16* __restrict__ fo2)
{
    const int b = blockIdx.x, t = threadIdx.x;
    __shared__ float red[256];
    __shared__ float pooled[64];
    const float* Sb = S + (size_t)b * C_ * 9;
    {
        const int o = t & 63, part = t >> 6, oo = o & 31;
        const float* cw = (o < 32) ? cw1 : cw2;
        const float* cwp = cw + (size_t)oo * (C_ * 9) + part * 128 * 9;
        const float* Sp  = Sb + part * 128 * 9;
        float s0 = 0.f, s1 = 0.f;
        #pragma unroll 4
        for (int k = 0; k < 1152; k += 2) {
            s0 = fmaf(cwp[k], Sp[k], s0);
            s1 = fmaf(cwp[k + 1], Sp[k + 1], s1);
        }
        red[t] = s0 + s1;
    }
    __syncthreads();
    if (t < 64) {
        float tot = red[t] + red[t + 64] + red[t + 128] + red[t + 192];
        float cb = (t < 32) ? cb1[t] : cb2[t - 32];
        pooled[t] = tot * (1.f / 4096.f) + cb;
    }
    __syncthreads();
    for (int j = t; j < 2 * 9216; j += 256) {
        const bool first = (j < 9216);
        const int jj = first ? j : j - 9216;
        const float* fw = first ? fw1 : fw2;
        const float* fb = first ? fb1 : fb2;
        const float* pp = pooled + (first ? 0 : 32);
        float v = fb[jj];
        const float4* fw4 = reinterpret_cast<const float4*>(fw + (size_t)jj * 32);
        #pragma unroll
        for (int q = 0; q < 8; q++) {
            float4 wv = fw4[q];
            v = fmaf(wv.x, pp[q * 4 + 0], v);
            v = fmaf(wv.y, pp[q * 4 + 1], v);
            v = fmaf(wv.z, pp[q * 4 + 2], v);
            v = fmaf(wv.w, pp[q * 4 + 3], v);
        }
        int oc = jj / 288;
        int r2 = jj - oc * 288;
        int ic = r2 / 9;
        int tap = r2 - ic * 9;
        int oidx = ((tap * 2 + (ic >> 4)) * 32 + oc) * 16 + (ic & 15);
        (first ? fo1 : fo2)[(size_t)b * 9216 + oidx] = __float2bfloat16_rn(v);
    }
}

// ============================================================================
// Both static weight transposes in one kernel
// ============================================================================
__global__ void wtrans2_kernel(const float* __restrict__ ds_w, const float* __restrict__ up_w,
                               __nv_bfloat16* __restrict__ wt_ds, __nv_bfloat16* __restrict__ wt_up)
{
    int gidx = blockIdx.x * 256 + threadIdx.x;   // 0..294911
    bool second = gidx >= 147456;
    int idx = second ? gidx - 147456 : gidx;
    const float* w = second ? up_w : ds_w;
    __nv_bfloat16* o = second ? wt_up : wt_ds;
    int cin = second ? IN_ : C_;
    int cout = second ? C_ : IN_;
    int i16 = idx & 15;
    int oc  = (idx >> 4) % cout;
    int rest = idx / (16 * cout);
    int nch = cin >> 4;
    int chunk = rest % nch;
    int tap = rest / nch;
    int ic = chunk * 16 + i16;
    o[idx] = __float2bfloat16_rn(w[((size_t)oc * cin + ic) * 9 + tap]);
}

// ============================================================================
__device__ __forceinline__ void mma16816(float* c, const uint32_t* a, const uint32_t* b)
{
    asm volatile(
        "mma.sync.aligned.m16n8k16.row.col.f32.bf16.bf16.f32 "
        "{%0,%1,%2,%3}, {%4,%5,%6,%7}, {%8,%9}, {%0,%1,%2,%3};\n"
        : "+f"(c[0]), "+f"(c[1]), "+f"(c[2]), "+f"(c[3])
        : "r"(a[0]), "r"(a[1]), "r"(a[2]), "r"(a[3]), "r"(b[0]), "r"(b[1]));
}

#define TILE_E 7128          // 6*66*18 bf16 elems
#define TILE_U 3564          // u32
#define WDS_U  2304          // 9*32*16 bf16 / 2

// ============================================================================
// ds conv: 512->32, split-K=3, fp32 input, fp32 partial output.
// Double-buffered smem + register prefetch, 1 sync/chunk.
// ============================================================================
__global__ void __launch_bounds__(256, 2)
conv_ds_kernel(const float* __restrict__ x, const __nv_bfloat16* __restrict__ wt,
               float* __restrict__ ypart)
{
    extern __shared__ __align__(16) char smraw[];
    __nv_bfloat16* s_x = reinterpret_cast<__nv_bfloat16*>(smraw);            // 2*TILE_E
    uint32_t* s_wu = reinterpret_cast<uint32_t*>(smraw + 2 * TILE_E * 2);    // 2*WDS_U u32

    const int b = blockIdx.z;
    const int s = blockIdx.y;
    const int ty = blockIdx.x * 4;
    const int t = threadIdx.x;
    const int wid = t >> 5, lane = t & 31, g = lane >> 2, t4 = lane & 3;
    const int chunk0 = s * 11, nch = (s == 2) ? 10 : 11;

    // zero pad columns (x = -1 and 64) in both buffers, once
    for (int e = t; e < 384; e += 256) {
        int buf = e >= 192; int r = e - buf * 192;
        int y_ = r >> 5; int ci = r & 31;
        int col = (ci >= 16) ? 65 : 0; int ic = ci & 15;
        s_x[buf * TILE_E + (y_ * 66 + col) * 18 + ic] = __float2bfloat16_rn(0.f);
    }

    // hoisted staging offsets (chunk-invariant)
    uint32_t gofs[6], sofs[6];
    bool pr[6];
    #pragma unroll
    for (int k = 0; k < 6; k++) {
        int idx = t + k * 256;           // float4 index, 0..1535
        int rowid = idx >> 4, xq = idx & 15;
        int ic = rowid / 6, y_ = rowid - ic * 6;
        int gy = ty + y_ - 1;
        pr[k] = ((unsigned)gy < 64u);
        gofs[k] = ic * NPIX_ + (pr[k] ? gy : 0) * 64 + xq * 4;
        sofs[k] = (y_ * 66 + 1 + xq * 4) * 18 + ic;
    }
    const float* xb = x + (size_t)b * C_ * NPIX_;
    const uint32_t* wsrc = reinterpret_cast<const uint32_t*>(wt);

    const int nb = wid * 32;
    int bBase[4];
    #pragma unroll
    for (int f = 0; f < 4; f++) {
        int n = nb + f * 8 + g;
        bBase[f] = ((n >> 6) * 66 + (n & 63)) * 9 + t4;
    }

    float acc[2][4][4];
    #pragma unroll
    for (int mf = 0; mf < 2; mf++)
        #pragma unroll
        for (int f = 0; f < 4; f++)
            #pragma unroll
            for (int q = 0; q < 4; q++) acc[mf][f][q] = 0.f;

    // stage chunk0 directly into buffer 0
    {
        const float* xc = xb + (size_t)chunk0 * 16 * NPIX_;
        #pragma unroll
        for (int k = 0; k < 6; k++) {
            float4 v = make_float4(0.f, 0.f, 0.f, 0.f);
            if (pr[k]) v = *reinterpret_cast<const float4*>(xc + gofs[k]);
            __nv_bfloat16* dst = s_x + sofs[k];
            dst[0]  = __float2bfloat16_rn(v.x);
            dst[18] = __float2bfloat16_rn(v.y);
            dst[36] = __float2bfloat16_rn(v.z);
            dst[54] = __float2bfloat16_rn(v.w);
        }
        #pragma unroll
        for (int k = 0; k < 9; k++)
            s_wu[k * 256 + t] = wsrc[(k * 32 + chunk0) * 256 + t];
    }
    __syncthreads();

    const uint32_t* s_xu = reinterpret_cast<const uint32_t*>(s_x);

    float4 xv[6];
    uint32_t wv[9];
    for (int c = chunk0; c < chunk0 + nch; c++) {
        const int cur = (c - chunk0) & 1;
        const bool more = (c + 1 < chunk0 + nch);
        if (more) {
            const float* xc = xb + (size_t)(c + 1) * 16 * NPIX_;
            #pragma unroll
            for (int k = 0; k < 6; k++) {
                xv[k] = make_float4(0.f, 0.f, 0.f, 0.f);
                if (pr[k]) xv[k] = *reinterpret_cast<const float4*>(xc + gofs[k]);
            }
            #pragma unroll
            for (int k = 0; k < 9; k++)
                wv[k] = wsrc[(k * 32 + (c + 1)) * 256 + t];
        }
        // compute on buffer cur
        {
            const uint32_t* xu = s_xu + cur * TILE_U;
            const uint32_t* au = s_wu + cur * WDS_U;
            #pragma unroll
            for (int tap = 0; tap < 9; tap++) {
                const int dy = tap / 3, dx = tap - dy * 3;
                uint32_t a[2][4];
                #pragma unroll
                for (int mf = 0; mf < 2; mf++) {
                    int base = (tap * 32 + mf * 16 + g) * 8 + t4;
                    a[mf][0] = au[base];
                    a[mf][1] = au[base + 64];
                    a[mf][2] = au[base + 4];
                    a[mf][3] = au[base + 68];
                }
                const int shift = (dy * 66 + dx) * 9;
                #pragma unroll
                for (int f = 0; f < 4; f++) {
                    uint32_t bfr[2];
                    int u = bBase[f] + shift;
                    bfr[0] = xu[u];
                    bfr[1] = xu[u + 4];
                    mma16816(acc[0][f], a[0], bfr);
                    mma16816(acc[1][f], a[1], bfr);
                }
            }
        }
        if (more) {
            const int nxt = cur ^ 1;
            #pragma unroll
            for (int k = 0; k < 6; k++) {
                __nv_bfloat16* dst = s_x + nxt * TILE_E + sofs[k];
                dst[0]  = __float2bfloat16_rn(xv[k].x);
                dst[18] = __float2bfloat16_rn(xv[k].y);
                dst[36] = __float2bfloat16_rn(xv[k].z);
                dst[54] = __float2bfloat16_rn(xv[k].w);
            }
            #pragma unroll
            for (int k = 0; k < 9; k++)
                s_wu[nxt * WDS_U + k * 256 + t] = wv[k];
            __syncthreads();
        }
    }

    // epilogue: fp32 partials
    float* yb = ypart + ((size_t)(s * B_ + b)) * (IN_ * NPIX_);
    #pragma unroll
    for (int mf = 0; mf < 2; mf++)
        #pragma unroll
        for (int rr = 0; rr < 2; rr++) {
            int oc = mf * 16 + g + rr * 8;
            #pragma unroll
            for (int f = 0; f < 4; f++) {
                int n = nb + f * 8 + t4 * 2;
                size_t off = (size_t)oc * NPIX_ + ty * 64 + n;
                *reinterpret_cast<float2*>(yb + off) =
                    make_float2(acc[mf][f][rr * 2], acc[mf][f][rr * 2 + 1]);
            }
        }
}

// ============================================================================
// cin=32 conv (dyn1, dyn2, up): stage BOTH chunks once, single sync.
// EPI: 1 = bf16 out, 2 = bf16+lrelu out, 3 = fp32 + bias + residual out
// ============================================================================
template <int MT, int NFRAG, int EPI>
__global__ void __launch_bounds__(256, 2)
conv_s2_kernel(const __nv_bfloat16* __restrict__ x, const __nv_bfloat16* __restrict__ wt,
               const float* __restrict__ bias, const float* __restrict__ resid,
               void* __restrict__ y, int cout, int wstride)
{
    extern __shared__ __align__(16) char smraw[];
    __nv_bfloat16* s_x = reinterpret_cast<__nv_bfloat16*>(smraw);          // 2*TILE_E
    __nv_bfloat16* s_a = reinterpret_cast<__nv_bfloat16*>(smraw + 2 * TILE_E * 2); // 18*MT*16

    const int b = blockIdx.z;
    const int ocb = blockIdx.y * MT;
    const int ty = blockIdx.x * 4;
    const int t = threadIdx.x;
    const int wid = t >> 5, lane = t & 31, g = lane >> 2, t4 = lane & 3;

    const int wm = (MT == 32) ? 0 : (wid >> 2) * 32;
    const int nb = (MT == 32) ? wid * 32 : (wid & 3) * 64;

    // zero pads in both chunk tiles
    for (int e = t; e < 384; e += 256) {
        int buf = e >= 192; int r = e - buf * 192;
        int y_ = r >> 5; int ci = r & 31;
        int col = (ci >= 16) ? 65 : 0; int ic = ci & 15;
        s_x[buf * TILE_E + (y_ * 66 + col) * 18 + ic] = __float2bfloat16_rn(0.f);
    }

    // stage both chunk tiles (uint4 = 8 px of one ic)
    const __nv_bfloat16* xb = x + (size_t)b * IN_ * NPIX_;
    #pragma unroll
    for (int k = 0; k < 6; k++) {
        int idx = t + k * 256;            // 0..1535
        int rowid = idx >> 3, xq = idx & 7;
        int ica = rowid / 6, y_ = rowid - ica * 6;   // ica 0..31
        int gy = ty + y_ - 1;
        uint4 v = make_uint4(0u, 0u, 0u, 0u);
        if ((unsigned)gy < 64u)
            v = *reinterpret_cast<const uint4*>(xb + (size_t)ica * NPIX_ + gy * 64 + xq * 8);
        int chunkid = ica >> 4, ic = ica & 15;
        __nv_bfloat16* dst = s_x + chunkid * TILE_E + (y_ * 66 + 1 + xq * 8) * 18 + ic;
        const __nv_bfloat16* sv = reinterpret_cast<const __nv_bfloat16*>(&v);
        #pragma unroll
        for (int j = 0; j < 8; j++) dst[18 * j] = sv[j];
    }

    // stage all weights [18 slices][MT][16]
    {
        const uint4* wsrc = reinterpret_cast<const uint4*>(wt + (size_t)b * wstride);
        uint4* s_a4 = reinterpret_cast<uint4*>(s_a);
        const int TOT4 = 18 * MT * 2;
        for (int u = t; u < TOT4; u += 256) {
            int slice = u / (MT * 2), j = u - slice * (MT * 2);
            s_a4[u] = wsrc[(size_t)slice * (cout * 2) + ocb * 2 + j];
        }
    }
    __syncthreads();

    int bBase[NFRAG];
    #pragma unroll
    for (int f = 0; f < NFRAG; f++) {
        int n = nb + f * 8 + g;
        bBase[f] = ((n >> 6) * 66 + (n & 63)) * 9 + t4;
    }

    float acc[2][NFRAG][4];
    #pragma unroll
    for (int mf = 0; mf < 2; mf++)
        #pragma unroll
        for (int f = 0; f < NFRAG; f++)
            #pragma unroll
            for (int q = 0; q < 4; q++) acc[mf][f][q] = 0.f;

    const uint32_t* s_xu = reinterpret_cast<const uint32_t*>(s_x);
    const uint32_t* s_au = reinterpret_cast<const uint32_t*>(s_a);

    #pragma unroll
    for (int cc = 0; cc < 2; cc++) {
        const uint32_t* xu = s_xu + cc * TILE_U;
        #pragma unroll
        for (int tap = 0; tap < 9; tap++) {
            const int dy = tap / 3, dx = tap - dy * 3;
            const int slice = tap * 2 + cc;
            uint32_t a[2][4];
            #pragma unroll
            for (int mf = 0; mf < 2; mf++) {
                int base = (slice * MT + wm + mf * 16 + g) * 8 + t4;
                a[mf][0] = s_au[base];
                a[mf][1] = s_au[base + 64];
                a[mf][2] = s_au[base + 4];
                a[mf][3] = s_au[base + 68];
            }
            const int shift = (dy * 66 + dx) * 9;
            #pragma unroll
            for (int f = 0; f < NFRAG; f++) {
                uint32_t bfr[2];
                int u = bBase[f] + shift;
                bfr[0] = xu[u];
                bfr[1] = xu[u + 4];
                mma16816(acc[0][f], a[0], bfr);
                mma16816(acc[1][f], a[1], bfr);
            }
        }
    }

    // epilogue
    #pragma unroll
    for (int mf = 0; mf < 2; mf++) {
        int oc0 = ocb + wm + mf * 16 + g;
        #pragma unroll
        for (int rr = 0; rr < 2; rr++) {
            int oc = oc0 + rr * 8;
            float bv = (EPI == 3) ? bias[oc] : 0.f;
            #pragma unroll
            for (int f = 0; f < NFRAG; f++) {
                int n = nb + f * 8 + t4 * 2;
                size_t off = (size_t)oc * NPIX_ + ty * 64 + n;
                float u0 = acc[mf][f][rr * 2 + 0];
                float u1 = acc[mf][f][rr * 2 + 1];
                if (EPI == 2) {
                    u0 = (u0 >= 0.f) ? u0 : 0.2f * u0;
                    u1 = (u1 >= 0.f) ? u1 : 0.2f * u1;
                }
                if (EPI == 3) {
                    float* yb = (float*)y + (size_t)b * cout * NPIX_;
                    float2 rv = *reinterpret_cast<const float2*>(
                        resid + (size_t)b * cout * NPIX_ + off);
                    *reinterpret_cast<float2*>(yb + off) =
                        make_float2(u0 + bv + rv.x, u1 + bv + rv.y);
                } else {
                    __nv_bfloat16* yb = (__nv_bfloat16*)y + (size_t)b * cout * NPIX_;
                    __nv_bfloat162 h;
                    h.x = __float2bfloat16_rn(u0);
                    h.y = __float2bfloat16_rn(u1);
                    *reinterpret_cast<__nv_bfloat162*>(yb + off) = h;
                }
            }
        }
    }
}

// ============================================================================
// Combine ds split-K partials + bias -> bf16 c0
// ============================================================================
__global__ void combine_kernel(const float* __restrict__ part,
                               const float* __restrict__ bias,
                               __nv_bfloat16* __restrict__ out)
{
    int i = blockIdx.x * 256 + threadIdx.x;
    const float4* p0 = reinterpret_cast<const float4*>(part);
    const float4* p1 = p0 + 262144;
    const float4* p2 = p1 + 262144;
    float4 a = p0[i], bq = p1[i], cq = p2[i];
    float bv = bias[(i >> 10) & 31];
    __nv_bfloat162 h0, h1;
    h0.x = __float2bfloat16_rn(a.x + bq.x + cq.x + bv);
    h0.y = __float2bfloat16_rn(a.y + bq.y + cq.y + bv);
    h1.x = __float2bfloat16_rn(a.z + bq.z + cq.z + bv);
    h1.y = __float2bfloat16_rn(a.w + bq.w + cq.w + bv);
    reinterpret_cast<__nv_bfloat162*>(out)[2 * i]     = h0;
    reinterpret_cast<__nv_bfloat162*>(out)[2 * i + 1] = h1;
}

// ============================================================================
extern "C" void kernel_launch(void* const* d_in, const int* in_sizes, int n_in,
                              void* d_out, int out_size)
{
    const float* content = (const float*)d_in[0];
    const float* style   = (const float*)d_in[1];
    const float* ds_w    = (const float*)d_in[2];
    const float* ds_b    = (const float*)d_in[3];
    const float* up_w    = (const float*)d_in[4];
    const float* up_b    = (const float*)d_in[5];
    const float* f1_cw   = (const float*)d_in[6];
    const float* f1_cb   = (const float*)d_in[7];
    const float* f1_fw   = (const float*)d_in[8];
    const float* f1_fb   = (const float*)d_in[9];
    const float* f2_cw   = (const float*)d_in[10];
    const float* f2_cb   = (const float*)d_in[11];
    const float* f2_fw   = (const float*)d_in[12];
    const float* f2_fb   = (const float*)d_in[13];
    float* out = (float*)d_out;

    float *pS, *pPart;
    __nv_bfloat16 *pF1, *pF2, *pC0, *pC1, *pC2, *pWds, *pWup;
    cudaGetSymbolAddress((void**)&pS,  g_S);
    cudaGetSymbolAddress((void**)&pF1, g_fbf1);
    cudaGetSymbolAddress((void**)&pF2, g_fbf2);
    cudaGetSymbolAddress((void**)&pC0, g_c0);
    cudaGetSymbolAddress((void**)&pC1, g_c1);
    cudaGetSymbolAddress((void**)&pC2, g_c2);
    cudaGetSymbolAddress((void**)&pPart, g_part);
    cudaGetSymbolAddress((void**)&pWds, g_wt_ds);
    cudaGetSymbolAddress((void**)&pWup, g_wt_up);

    const int SM_DS  = 2 * TILE_E * 2 + 2 * WDS_U * 4;        // 46944
    const int SM_DYN = 2 * TILE_E * 2 + 18 * 32 * 16 * 2;     // 46944
    const int SM_UP  = 2 * TILE_E * 2 + 18 * 64 * 16 * 2;     // 65376

    cudaFuncSetAttribute(conv_ds_kernel, cudaFuncAttributeMaxDynamicSharedMemorySize, SM_DS);
    cudaFuncSetAttribute(conv_s2_kernel<32, 4, 2>, cudaFuncAttributeMaxDynamicSharedMemorySize, SM_DYN);
    cudaFuncSetAttribute(conv_s2_kernel<32, 4, 1>, cudaFuncAttributeMaxDynamicSharedMemorySize, SM_DYN);
    cudaFuncSetAttribute(conv_s2_kernel<64, 8, 3>, cudaFuncAttributeMaxDynamicSharedMemorySize, SM_UP);

    style_reduce_kernel<<<dim3(C_, B_), 256>>>(style, pS);
    predict_kernel<<<B_, 256>>>(pS, f1_cw, f1_cb, f1_fw, f1_fb,
                                    f2_cw, f2_cb, f2_fw, f2_fb, pF1, pF2);
    wtrans2_kernel<<<1152, 256>>>(ds_w, up_w, pWds, pWup);

    conv_ds_kernel<<<dim3(16, 3, B_), 256, SM_DS>>>(content, pWds, pPart);
    combine_kernel<<<1024, 256>>>(pPart, ds_b, pC0);

    conv_s2_kernel<32, 4, 2><<<dim3(16, 1, B_), 256, SM_DYN>>>(
        pC0, pF1, nullptr, nullptr, pC1, IN_, 9216);
    conv_s2_kernel<32, 4, 1><<<dim3(16, 1, B_), 256, SM_DYN>>>(
        pC1, pF2, nullptr, nullptr, pC2, IN_, 9216);

    conv_s2_kernel<64, 8, 3><<<dim3(16, 8, B_), 256, SM_UP>>>(
        pC2, pWup, up_b, content, out, C_, 0);
}